// round 4
// baseline (speedup 1.0000x reference)
#include <cuda_runtime.h>
#include <cuda_bf16.h>

#define NP   64
#define NANG 2016      // 64*63/2
#define TPB  256

// R stored k-major, row-scaled: g_R[k*64 + i] = mus[i] * R[i][k]
__device__ float g_R[NP * NP];

// ---------------------------------------------------------------------------
// f32x2 packed helpers (sm_103a FFMA2 via PTX)
// ---------------------------------------------------------------------------
__device__ __forceinline__ unsigned long long ffma2(unsigned long long a,
                                                    unsigned long long b,
                                                    unsigned long long c) {
    unsigned long long d;
    asm("fma.rn.f32x2 %0, %1, %2, %3;" : "=l"(d) : "l"(a), "l"(b), "l"(c));
    return d;
}
__device__ __forceinline__ unsigned long long splat2(float x) {
    unsigned long long d;
    asm("mov.b64 %0, {%1, %1};" : "=l"(d) : "f"(x));
    return d;
}
__device__ __forceinline__ float2 unpack2(unsigned long long v) {
    float2 r;
    asm("mov.b64 {%0, %1}, %2;" : "=f"(r.x), "=f"(r.y) : "l"(v));
    return r;
}

// ---------------------------------------------------------------------------
// Kernel 1: build composite rotation matrix R.
// v2: SMALL dynamic loop (avoids the 190KB-SASS single-CTA I$-starve of the
// fully-unrolled version). Thread j owns column j, kept in shared Y[:, j];
// only the inner-loop-carried vt lives in a register, so the dependence
// chain is one FFMA (4 cyc) per rotation and all LDS are off-chain.
// ---------------------------------------------------------------------------
__global__ void build_R_kernel(const float* __restrict__ angles,
                               const float* __restrict__ mus) {
    __shared__ float2 cs[NANG];
    __shared__ float  Y[NP][NP];   // Y[i][j] = R[i][j] (column j owned by thread j)
    const int tid = threadIdx.x;   // 0..63

    for (int a = tid; a < NANG; a += NP) {
        float s, c;
        sincosf(angles[a], &s, &c);
        cs[a] = make_float2(c, s);
    }
#pragma unroll
    for (int i = 0; i < NP; ++i) Y[i][tid] = (i == tid) ? 1.0f : 0.0f;
    __syncthreads();

    // Each thread touches only its own column -> no cross-thread races.
    int idx = 0;
    for (int it = 0; it < NP - 1; ++it) {
        float vt = Y[it][tid];
#pragma unroll 4
        for (int ib = it + 1; ib < NP; ++ib) {
            float2 a = cs[idx];
            ++idx;
            float vb = Y[ib][tid];
            float nb = fmaf(a.y, vt, a.x * vb);   // vb' = s*vt + c*vb (old vt)
            vt = fmaf(a.x, vt, -a.y * vb);        // vt' = c*vt - s*vb
            Y[ib][tid] = nb;
        }
        Y[it][tid] = vt;
    }
    __syncthreads();

    // g_R[k*64+i] = mus[i] * R[i][k]; thread tid writes k = tid.
    for (int i = 0; i < NP; ++i) {
        g_R[tid * NP + i] = Y[i][tid] * mus[i];
    }
}

// ---------------------------------------------------------------------------
// Kernel 2: out[64, N] = R @ X via f32x2 packed FMA + software-pipelined
// double-buffered LDG so the ~830-cyc memory time of each k-block overlaps
// the ~1024-cyc fma-pipe time of the previous one.
// Tile: 256 threads = 4 row-groups x 64 col-slots; thread = 16 rows x 4 cols.
// ---------------------------------------------------------------------------
__global__ __launch_bounds__(TPB, 2)
void apply_R_kernel(const float* __restrict__ X,
                    float* __restrict__ out,
                    int N) {
    __shared__ __align__(16) float Rs[NP * NP];
    for (int t = threadIdx.x; t < NP * NP; t += TPB) Rs[t] = g_R[t];
    __syncthreads();

    const int rg  = threadIdx.x >> 6;          // row group 0..3
    const int cl  = threadIdx.x & 63;          // column slot
    const int col = blockIdx.x * TPB + cl * 4;
    if (col >= N) return;                      // N % 4 == 0

    unsigned long long acc[8][4];
#pragma unroll
    for (int p = 0; p < 8; ++p)
#pragma unroll
        for (int j = 0; j < 4; ++j) acc[p][j] = 0ull;

    const ulonglong2* Rs2 = reinterpret_cast<const ulonglong2*>(Rs);
    const int rbase = rg * 4;
    const float* xp = X + col;

#define DO_K(kk, xv)                                                             \
    {                                                                            \
        unsigned long long xs0 = splat2((xv).x);                                 \
        unsigned long long xs1 = splat2((xv).y);                                 \
        unsigned long long xs2 = splat2((xv).z);                                 \
        unsigned long long xs3 = splat2((xv).w);                                 \
        ulonglong2 q0 = Rs2[(kk) * 16 + rbase + 0];                              \
        ulonglong2 q1 = Rs2[(kk) * 16 + rbase + 1];                              \
        ulonglong2 q2 = Rs2[(kk) * 16 + rbase + 2];                              \
        ulonglong2 q3 = Rs2[(kk) * 16 + rbase + 3];                              \
        acc[0][0] = ffma2(q0.x, xs0, acc[0][0]);                                 \
        acc[0][1] = ffma2(q0.x, xs1, acc[0][1]);                                 \
        acc[0][2] = ffma2(q0.x, xs2, acc[0][2]);                                 \
        acc[0][3] = ffma2(q0.x, xs3, acc[0][3]);                                 \
        acc[1][0] = ffma2(q0.y, xs0, acc[1][0]);                                 \
        acc[1][1] = ffma2(q0.y, xs1, acc[1][1]);                                 \
        acc[1][2] = ffma2(q0.y, xs2, acc[1][2]);                                 \
        acc[1][3] = ffma2(q0.y, xs3, acc[1][3]);                                 \
        acc[2][0] = ffma2(q1.x, xs0, acc[2][0]);                                 \
        acc[2][1] = ffma2(q1.x, xs1, acc[2][1]);                                 \
        acc[2][2] = ffma2(q1.x, xs2, acc[2][2]);                                 \
        acc[2][3] = ffma2(q1.x, xs3, acc[2][3]);                                 \
        acc[3][0] = ffma2(q1.y, xs0, acc[3][0]);                                 \
        acc[3][1] = ffma2(q1.y, xs1, acc[3][1]);                                 \
        acc[3][2] = ffma2(q1.y, xs2, acc[3][2]);                                 \
        acc[3][3] = ffma2(q1.y, xs3, acc[3][3]);                                 \
        acc[4][0] = ffma2(q2.x, xs0, acc[4][0]);                                 \
        acc[4][1] = ffma2(q2.x, xs1, acc[4][1]);                                 \
        acc[4][2] = ffma2(q2.x, xs2, acc[4][2]);                                 \
        acc[4][3] = ffma2(q2.x, xs3, acc[4][3]);                                 \
        acc[5][0] = ffma2(q2.y, xs0, acc[5][0]);                                 \
        acc[5][1] = ffma2(q2.y, xs1, acc[5][1]);                                 \
        acc[5][2] = ffma2(q2.y, xs2, acc[5][2]);                                 \
        acc[5][3] = ffma2(q2.y, xs3, acc[5][3]);                                 \
        acc[6][0] = ffma2(q3.x, xs0, acc[6][0]);                                 \
        acc[6][1] = ffma2(q3.x, xs1, acc[6][1]);                                 \
        acc[6][2] = ffma2(q3.x, xs2, acc[6][2]);                                 \
        acc[6][3] = ffma2(q3.x, xs3, acc[6][3]);                                 \
        acc[7][0] = ffma2(q3.y, xs0, acc[7][0]);                                 \
        acc[7][1] = ffma2(q3.y, xs1, acc[7][1]);                                 \
        acc[7][2] = ffma2(q3.y, xs2, acc[7][2]);                                 \
        acc[7][3] = ffma2(q3.y, xs3, acc[7][3]);                                 \
    }

    // Prologue: load k-block 0
    float4 ca = *reinterpret_cast<const float4*>(xp + (size_t)0 * N);
    float4 cb = *reinterpret_cast<const float4*>(xp + (size_t)1 * N);
    float4 cc = *reinterpret_cast<const float4*>(xp + (size_t)2 * N);
    float4 cd = *reinterpret_cast<const float4*>(xp + (size_t)3 * N);

#pragma unroll 1
    for (int kb = 0; kb < NP; kb += 4) {
        // Prefetch next k-block FIRST (wraps to 0..3 on the last iter; the
        // redundant load is discarded). 4 outstanding LDG.128 overlap the
        // ~1024-cyc FFMA2 burst below.
        const int kn = (kb + 4) & (NP - 1);
        float4 na = *reinterpret_cast<const float4*>(xp + (size_t)(kn + 0) * N);
        float4 nb = *reinterpret_cast<const float4*>(xp + (size_t)(kn + 1) * N);
        float4 nc = *reinterpret_cast<const float4*>(xp + (size_t)(kn + 2) * N);
        float4 nd = *reinterpret_cast<const float4*>(xp + (size_t)(kn + 3) * N);

        DO_K(kb + 0, ca);
        DO_K(kb + 1, cb);
        DO_K(kb + 2, cc);
        DO_K(kb + 3, cd);

        ca = na; cb = nb; cc = nc; cd = nd;
    }
#undef DO_K

    const int row0 = rg * 16;
#pragma unroll
    for (int p = 0; p < 8; ++p) {
        float2 u0 = unpack2(acc[p][0]);
        float2 u1 = unpack2(acc[p][1]);
        float2 u2 = unpack2(acc[p][2]);
        float2 u3 = unpack2(acc[p][3]);
        float4 lo = make_float4(u0.x, u1.x, u2.x, u3.x);
        float4 hi = make_float4(u0.y, u1.y, u2.y, u3.y);
        *reinterpret_cast<float4*>(out + (size_t)(row0 + 2 * p + 0) * N + col) = lo;
        *reinterpret_cast<float4*>(out + (size_t)(row0 + 2 * p + 1) * N + col) = hi;
    }
}

// ---------------------------------------------------------------------------
// Inputs (metadata order): X [64*500000] f32, angles [2016] f32, mus [64] f32.
// Output: [64*500000] f32.
// ---------------------------------------------------------------------------
extern "C" void kernel_launch(void* const* d_in, const int* in_sizes, int n_in,
                              void* d_out, int out_size) {
    const float* X      = (const float*)d_in[0];
    const float* angles = (const float*)d_in[1];
    const float* mus    = (const float*)d_in[2];
    float* out = (float*)d_out;

    const int N = in_sizes[0] / NP;  // 500000

    build_R_kernel<<<1, NP>>>(angles, mus);

    int grid = (N + TPB - 1) / TPB;
    apply_R_kernel<<<grid, TPB>>>(X, out, N);
}

// round 5
// speedup vs baseline: 1.3905x; 1.3905x over previous
#include <cuda_runtime.h>
#include <cuda_bf16.h>

#define NP   64
#define NANG 2016      // 64*63/2
#define TPB  256
#define CPB  128       // columns per block (2 per thread)

// R stored k-major, row-scaled: g_R[k*64 + i] = mus[i] * R[i][k]
__device__ float g_R[NP * NP];

// ---------------------------------------------------------------------------
// f32x2 packed helpers (sm_103a FFMA2 via PTX)
// ---------------------------------------------------------------------------
__device__ __forceinline__ unsigned long long ffma2(unsigned long long a,
                                                    unsigned long long b,
                                                    unsigned long long c) {
    unsigned long long d;
    asm("fma.rn.f32x2 %0, %1, %2, %3;" : "=l"(d) : "l"(a), "l"(b), "l"(c));
    return d;
}
__device__ __forceinline__ unsigned long long splat2(float x) {
    unsigned long long d;
    asm("mov.b64 %0, {%1, %1};" : "=l"(d) : "f"(x));
    return d;
}
__device__ __forceinline__ float2 unpack2(unsigned long long v) {
    float2 r;
    asm("mov.b64 {%0, %1}, %2;" : "=f"(r.x), "=f"(r.y) : "l"(v));
    return r;
}

// ---------------------------------------------------------------------------
// Kernel 1: build composite rotation matrix R (1 block, 64 threads).
// REVERTED to the fully-unrolled register version (R1/R3): thread j holds
// column j in r[64] with static indices; chain = 1 dependent FFMA (4 cyc)
// per rotation. The shared-memory dynamic-loop variant (R4) exposed 29-cyc
// LDS latency per rotation because ptxas cannot hoist LDS past STS.
// ---------------------------------------------------------------------------
__global__ void build_R_kernel(const float* __restrict__ angles,
                               const float* __restrict__ mus) {
    __shared__ float2 cs[NANG];
    const int tid = threadIdx.x;  // 0..63 = column index of R

    for (int a = tid; a < NANG; a += NP) {
        float s, c;
        sincosf(angles[a], &s, &c);
        cs[a] = make_float2(c, s);
    }
    __syncthreads();

    float r[NP];
#pragma unroll
    for (int i = 0; i < NP; ++i) r[i] = (i == tid) ? 1.0f : 0.0f;

    int idx = 0;
#pragma unroll
    for (int it = 0; it < NP - 1; ++it) {
#pragma unroll
        for (int ib = it + 1; ib < NP; ++ib) {
            float2 a = cs[idx];
            ++idx;
            float vt = r[it];
            float vb = r[ib];
            r[it] = fmaf(a.x, vt, -a.y * vb);
            r[ib] = fmaf(a.y, vt,  a.x * vb);
        }
    }

#pragma unroll
    for (int i = 0; i < NP; ++i) g_R[tid * NP + i] = r[i] * mus[i];
}

// ---------------------------------------------------------------------------
// Kernel 2: out[64, N] = R @ X via f32x2 packed FMA.
// v3 tile: 256 threads = 4 row-groups x 64 col-slots; thread = 16 rows x
// 2 cols (acc = 32 regs) -> 3 blocks/SM (24 warps). k processed in batches
// of 8: 8 LDG.64 issued up front (MLP=8) before the 128-FFMA2 burst.
// R row-pairs via broadcast LDS.128 with immediate offsets (full unroll).
// ---------------------------------------------------------------------------
__global__ __launch_bounds__(TPB, 3)
void apply_R_kernel(const float* __restrict__ X,
                    float* __restrict__ out,
                    int N) {
    __shared__ __align__(16) float Rs[NP * NP];
    for (int t = threadIdx.x; t < NP * NP; t += TPB) Rs[t] = g_R[t];
    __syncthreads();

    const int rg  = threadIdx.x >> 6;          // row group 0..3
    const int cl  = threadIdx.x & 63;          // column slot
    const int col = blockIdx.x * CPB + cl * 2; // 128 columns per block
    if (col >= N) return;                      // N % 2 == 0

    // acc[p][j]: f32x2 over rows (rg*16+2p, rg*16+2p+1), column col+j
    unsigned long long acc[8][2];
#pragma unroll
    for (int p = 0; p < 8; ++p) {
        acc[p][0] = 0ull;
        acc[p][1] = 0ull;
    }

    const ulonglong2* Rs2 = reinterpret_cast<const ulonglong2*>(Rs);
    const int rbase = rg * 4;
    const float* xp = X + col;

#define DO_K(kk, xv)                                                   \
    {                                                                  \
        unsigned long long xs0 = splat2((xv).x);                       \
        unsigned long long xs1 = splat2((xv).y);                       \
        ulonglong2 q0 = Rs2[(kk) * 16 + rbase + 0];                    \
        ulonglong2 q1 = Rs2[(kk) * 16 + rbase + 1];                    \
        ulonglong2 q2 = Rs2[(kk) * 16 + rbase + 2];                    \
        ulonglong2 q3 = Rs2[(kk) * 16 + rbase + 3];                    \
        acc[0][0] = ffma2(q0.x, xs0, acc[0][0]);                       \
        acc[0][1] = ffma2(q0.x, xs1, acc[0][1]);                       \
        acc[1][0] = ffma2(q0.y, xs0, acc[1][0]);                       \
        acc[1][1] = ffma2(q0.y, xs1, acc[1][1]);                       \
        acc[2][0] = ffma2(q1.x, xs0, acc[2][0]);                       \
        acc[2][1] = ffma2(q1.x, xs1, acc[2][1]);                       \
        acc[3][0] = ffma2(q1.y, xs0, acc[3][0]);                       \
        acc[3][1] = ffma2(q1.y, xs1, acc[3][1]);                       \
        acc[4][0] = ffma2(q2.x, xs0, acc[4][0]);                       \
        acc[4][1] = ffma2(q2.x, xs1, acc[4][1]);                       \
        acc[5][0] = ffma2(q2.y, xs0, acc[5][0]);                       \
        acc[5][1] = ffma2(q2.y, xs1, acc[5][1]);                       \
        acc[6][0] = ffma2(q3.x, xs0, acc[6][0]);                       \
        acc[6][1] = ffma2(q3.x, xs1, acc[6][1]);                       \
        acc[7][0] = ffma2(q3.y, xs0, acc[7][0]);                       \
        acc[7][1] = ffma2(q3.y, xs1, acc[7][1]);                       \
    }

#pragma unroll 1
    for (int kb = 0; kb < NP; kb += 8) {
        // 8 outstanding LDG.64 (MLP=8) before the 128-FFMA2 burst.
        float2 xv[8];
#pragma unroll
        for (int u = 0; u < 8; ++u) {
            xv[u] = *reinterpret_cast<const float2*>(xp + (size_t)(kb + u) * N);
        }
#pragma unroll
        for (int u = 0; u < 8; ++u) {
            DO_K(kb + u, xv[u]);
        }
    }
#undef DO_K

    // Write out: unpack row pairs, store float2 per row (coalesced 512B/warp).
    const int row0 = rg * 16;
#pragma unroll
    for (int p = 0; p < 8; ++p) {
        float2 u0 = unpack2(acc[p][0]);
        float2 u1 = unpack2(acc[p][1]);
        float2 lo = make_float2(u0.x, u1.x);
        float2 hi = make_float2(u0.y, u1.y);
        *reinterpret_cast<float2*>(out + (size_t)(row0 + 2 * p + 0) * N + col) = lo;
        *reinterpret_cast<float2*>(out + (size_t)(row0 + 2 * p + 1) * N + col) = hi;
    }
}

// ---------------------------------------------------------------------------
// Inputs (metadata order): X [64*500000] f32, angles [2016] f32, mus [64] f32.
// Output: [64*500000] f32.
// ---------------------------------------------------------------------------
extern "C" void kernel_launch(void* const* d_in, const int* in_sizes, int n_in,
                              void* d_out, int out_size) {
    const float* X      = (const float*)d_in[0];
    const float* angles = (const float*)d_in[1];
    const float* mus    = (const float*)d_in[2];
    float* out = (float*)d_out;

    const int N = in_sizes[0] / NP;  // 500000

    build_R_kernel<<<1, NP>>>(angles, mus);

    int grid = (N + CPB - 1) / CPB;  // 128 columns per block
    apply_R_kernel<<<grid, TPB>>>(X, out, N);
}

// round 6
// speedup vs baseline: 1.4888x; 1.0707x over previous
#include <cuda_runtime.h>
#include <cuda_bf16.h>

#define NP   64
#define NANG 2016      // 64*63/2
#define TPB  256
#define CPB  128       // columns per block (2 per thread)

// R stored k-major, row-scaled: g_R[k*64 + i] = mus[i] * R[i][k]
__device__ float g_R[NP * NP];

// ---------------------------------------------------------------------------
// f32x2 packed helpers (sm_103a FFMA2 via PTX)
// ---------------------------------------------------------------------------
__device__ __forceinline__ unsigned long long ffma2(unsigned long long a,
                                                    unsigned long long b,
                                                    unsigned long long c) {
    unsigned long long d;
    asm("fma.rn.f32x2 %0, %1, %2, %3;" : "=l"(d) : "l"(a), "l"(b), "l"(c));
    return d;
}
__device__ __forceinline__ unsigned long long splat2(float x) {
    unsigned long long d;
    asm("mov.b64 %0, {%1, %1};" : "=l"(d) : "f"(x));
    return d;
}
__device__ __forceinline__ float2 unpack2(unsigned long long v) {
    float2 r;
    asm("mov.b64 {%0, %1}, %2;" : "=f"(r.x), "=f"(r.y) : "l"(v));
    return r;
}

// ---------------------------------------------------------------------------
// Kernel 1: build composite rotation matrix R.
// Fully-unrolled register version (column j in r[64], static indices,
// 4-cyc FFMA chain per rotation). Launched at grid=148 with every block
// doing IDENTICAL work and writing identical values: the ~130KB SASS body
// at grid=1 triggers the sm_103a single-CTA issue throttle (costing ~60us);
// the throttle vanishes at grid>=148. Redundant writes are benign
// (bit-identical, deterministic).
// ---------------------------------------------------------------------------
__global__ void build_R_kernel(const float* __restrict__ angles,
                               const float* __restrict__ mus) {
    __shared__ float2 cs[NANG];
    const int tid = threadIdx.x;  // 0..63 = column index of R

    for (int a = tid; a < NANG; a += NP) {
        float s, c;
        sincosf(angles[a], &s, &c);
        cs[a] = make_float2(c, s);
    }
    __syncthreads();

    float r[NP];
#pragma unroll
    for (int i = 0; i < NP; ++i) r[i] = (i == tid) ? 1.0f : 0.0f;

    int idx = 0;
#pragma unroll
    for (int it = 0; it < NP - 1; ++it) {
#pragma unroll
        for (int ib = it + 1; ib < NP; ++ib) {
            float2 a = cs[idx];
            ++idx;
            float vt = r[it];
            float vb = r[ib];
            r[it] = fmaf(a.x, vt, -a.y * vb);
            r[ib] = fmaf(a.y, vt,  a.x * vb);
        }
    }

#pragma unroll
    for (int i = 0; i < NP; ++i) g_R[tid * NP + i] = r[i] * mus[i];
}

// ---------------------------------------------------------------------------
// Kernel 2: out[64, N] = R @ X via f32x2 packed FMA.
// Tile: 256 threads = 4 row-groups x 64 col-slots; thread = 16 rows x 2 cols.
// k runs in 8 batches of 8; batches are ping-pong software-pipelined with
// ALL indices compile-time static: batch b+1's 8 LDG.64 issue before batch
// b's 128 FFMA2s, so the ~577cyc DRAM latency is covered by compute.
// ---------------------------------------------------------------------------
__global__ __launch_bounds__(TPB, 3)
void apply_R_kernel(const float* __restrict__ X,
                    float* __restrict__ out,
                    int N) {
    __shared__ __align__(16) float Rs[NP * NP];
    for (int t = threadIdx.x; t < NP * NP; t += TPB) Rs[t] = g_R[t];
    __syncthreads();

    const int rg  = threadIdx.x >> 6;          // row group 0..3
    const int cl  = threadIdx.x & 63;          // column slot
    const int col = blockIdx.x * CPB + cl * 2;
    if (col >= N) return;                      // N % 2 == 0

    unsigned long long acc[8][2];
#pragma unroll
    for (int p = 0; p < 8; ++p) {
        acc[p][0] = 0ull;
        acc[p][1] = 0ull;
    }

    const ulonglong2* Rs2 = reinterpret_cast<const ulonglong2*>(Rs);
    const int rbase = rg * 4;
    const float* xp = X + col;

#define DO_K(kk, xv)                                                   \
    {                                                                  \
        unsigned long long xs0 = splat2((xv).x);                       \
        unsigned long long xs1 = splat2((xv).y);                       \
        ulonglong2 q0 = Rs2[(kk) * 16 + rbase + 0];                    \
        ulonglong2 q1 = Rs2[(kk) * 16 + rbase + 1];                    \
        ulonglong2 q2 = Rs2[(kk) * 16 + rbase + 2];                    \
        ulonglong2 q3 = Rs2[(kk) * 16 + rbase + 3];                    \
        acc[0][0] = ffma2(q0.x, xs0, acc[0][0]);                       \
        acc[0][1] = ffma2(q0.x, xs1, acc[0][1]);                       \
        acc[1][0] = ffma2(q0.y, xs0, acc[1][0]);                       \
        acc[1][1] = ffma2(q0.y, xs1, acc[1][1]);                       \
        acc[2][0] = ffma2(q1.x, xs0, acc[2][0]);                       \
        acc[2][1] = ffma2(q1.x, xs1, acc[2][1]);                       \
        acc[3][0] = ffma2(q1.y, xs0, acc[3][0]);                       \
        acc[3][1] = ffma2(q1.y, xs1, acc[3][1]);                       \
        acc[4][0] = ffma2(q2.x, xs0, acc[4][0]);                       \
        acc[4][1] = ffma2(q2.x, xs1, acc[4][1]);                       \
        acc[5][0] = ffma2(q2.y, xs0, acc[5][0]);                       \
        acc[5][1] = ffma2(q2.y, xs1, acc[5][1]);                       \
        acc[6][0] = ffma2(q3.x, xs0, acc[6][0]);                       \
        acc[6][1] = ffma2(q3.x, xs1, acc[6][1]);                       \
        acc[7][0] = ffma2(q3.y, xs0, acc[7][0]);                       \
        acc[7][1] = ffma2(q3.y, xs1, acc[7][1]);                       \
    }

    // Load one batch of 8 k-values (8 outstanding LDG.64, static offsets).
#define LOADB(buf, b)                                                            \
    {                                                                            \
        _Pragma("unroll")                                                        \
        for (int u = 0; u < 8; ++u) {                                            \
            (buf)[u] = *reinterpret_cast<const float2*>(                         \
                xp + (size_t)((b) * 8 + u) * N);                                 \
        }                                                                        \
    }
#define COMPUTEB(buf, b)                                                         \
    {                                                                            \
        _Pragma("unroll")                                                        \
        for (int u = 0; u < 8; ++u) { DO_K((b) * 8 + u, (buf)[u]); }             \
    }

    float2 bufA[8], bufB[8];
    LOADB(bufA, 0);
#pragma unroll
    for (int bb = 0; bb < 4; ++bb) {
        const int b0 = 2 * bb, b1 = 2 * bb + 1;
        LOADB(bufB, b1);        // prefetch odd batch
        COMPUTEB(bufA, b0);     // consume even batch (loads issued last iter)
        if (b1 + 1 < 8) LOADB(bufA, b1 + 1);  // prefetch next even batch
        COMPUTEB(bufB, b1);     // consume odd batch
    }
#undef COMPUTEB
#undef LOADB
#undef DO_K

    const int row0 = rg * 16;
#pragma unroll
    for (int p = 0; p < 8; ++p) {
        float2 u0 = unpack2(acc[p][0]);
        float2 u1 = unpack2(acc[p][1]);
        float2 lo = make_float2(u0.x, u1.x);
        float2 hi = make_float2(u0.y, u1.y);
        *reinterpret_cast<float2*>(out + (size_t)(row0 + 2 * p + 0) * N + col) = lo;
        *reinterpret_cast<float2*>(out + (size_t)(row0 + 2 * p + 1) * N + col) = hi;
    }
}

// ---------------------------------------------------------------------------
// Inputs (metadata order): X [64*500000] f32, angles [2016] f32, mus [64] f32.
// Output: [64*500000] f32.
// ---------------------------------------------------------------------------
extern "C" void kernel_launch(void* const* d_in, const int* in_sizes, int n_in,
                              void* d_out, int out_size) {
    const float* X      = (const float*)d_in[0];
    const float* angles = (const float*)d_in[1];
    const float* mus    = (const float*)d_in[2];
    float* out = (float*)d_out;

    const int N = in_sizes[0] / NP;  // 500000

    // grid=148: identical redundant work per block to defeat the low-grid
    // single-CTA issue throttle on the large unrolled body.
    build_R_kernel<<<148, NP>>>(angles, mus);

    int grid = (N + CPB - 1) / CPB;  // 128 columns per block
    apply_R_kernel<<<grid, TPB>>>(X, out, N);
}

// round 8
// speedup vs baseline: 1.7166x; 1.1530x over previous
#include <cuda_runtime.h>
#include <cuda_bf16.h>

#define NP   64
#define NANG 2016      // 64*63/2
#define TPB  256
#define CPB  128       // columns per block (2 per thread)

// R stored k-major, row-scaled: g_R[k*64 + i] = mus[i] * R[i][k]
__device__ float g_R[NP * NP];

// ---------------------------------------------------------------------------
// f32x2 packed helpers (sm_103a FFMA2 via PTX)
// ---------------------------------------------------------------------------
__device__ __forceinline__ unsigned long long ffma2(unsigned long long a,
                                                    unsigned long long b,
                                                    unsigned long long c) {
    unsigned long long d;
    asm("fma.rn.f32x2 %0, %1, %2, %3;" : "=l"(d) : "l"(a), "l"(b), "l"(c));
    return d;
}
__device__ __forceinline__ unsigned long long splat2(float x) {
    unsigned long long d;
    asm("mov.b64 %0, {%1, %1};" : "=l"(d) : "f"(x));
    return d;
}
__device__ __forceinline__ float2 unpack2(unsigned long long v) {
    float2 r;
    asm("mov.b64 {%0, %1}, %2;" : "=f"(r.x), "=f"(r.y) : "l"(v));
    return r;
}

// ---------------------------------------------------------------------------
// Kernel 1: build composite rotation matrix R — SMALL-CODE version.
// Thread j owns column j (in shared Y[:, j]). For fan t the chained value vt
// stays in a register; vb's are processed in blocks of 8 with all 8 LDS
// issued BEFORE the 8-FFMA chain (32 cyc) so the 29-cyc LDS latency is
// hidden, and the 8 STS follow (no load-after-store ordering hazard).
// Loop body ~2KB SASS vs ~160KB fully unrolled -> kills the I-fetch wall.
// ---------------------------------------------------------------------------
__global__ void build_R_kernel(const float* __restrict__ angles,
                               const float* __restrict__ mus) {
    __shared__ float2 cs[NANG];
    __shared__ float  Y[NP][NP];   // Y[row][col]; thread tid owns column tid
    const int tid = threadIdx.x;   // 0..63

    for (int a = tid; a < NANG; a += NP) {
        float s, c;
        sincosf(angles[a], &s, &c);
        cs[a] = make_float2(c, s);
    }
#pragma unroll
    for (int i = 0; i < NP; ++i) Y[i][tid] = (i == tid) ? 1.0f : 0.0f;
    __syncthreads();

    int idx = 0;
    for (int t = 0; t < NP - 1; ++t) {
        float vt = Y[t][tid];
        int ib = t + 1;

        // Remainder so the main loop runs whole 8-blocks.
        const int rem = (NP - ib) & 7;
        for (int u = 0; u < rem; ++u) {
            float2 a = cs[idx + u];
            float vb = Y[ib + u][tid];
            float nb = fmaf(a.y, vt, a.x * vb);
            vt = fmaf(a.x, vt, -a.y * vb);
            Y[ib + u][tid] = nb;
        }
        idx += rem;
        ib  += rem;

        for (; ib < NP; ib += 8, idx += 8) {
            // 8 independent LDS issued up front (plus broadcast cs loads).
            float2 a0 = cs[idx + 0], a1 = cs[idx + 1], a2 = cs[idx + 2], a3 = cs[idx + 3];
            float2 a4 = cs[idx + 4], a5 = cs[idx + 5], a6 = cs[idx + 6], a7 = cs[idx + 7];
            float vb0 = Y[ib + 0][tid], vb1 = Y[ib + 1][tid];
            float vb2 = Y[ib + 2][tid], vb3 = Y[ib + 3][tid];
            float vb4 = Y[ib + 4][tid], vb5 = Y[ib + 5][tid];
            float vb6 = Y[ib + 6][tid], vb7 = Y[ib + 7][tid];

            // 8-rotation register chain (4 cyc/step).
            float nb0 = fmaf(a0.y, vt, a0.x * vb0); vt = fmaf(a0.x, vt, -a0.y * vb0);
            float nb1 = fmaf(a1.y, vt, a1.x * vb1); vt = fmaf(a1.x, vt, -a1.y * vb1);
            float nb2 = fmaf(a2.y, vt, a2.x * vb2); vt = fmaf(a2.x, vt, -a2.y * vb2);
            float nb3 = fmaf(a3.y, vt, a3.x * vb3); vt = fmaf(a3.x, vt, -a3.y * vb3);
            float nb4 = fmaf(a4.y, vt, a4.x * vb4); vt = fmaf(a4.x, vt, -a4.y * vb4);
            float nb5 = fmaf(a5.y, vt, a5.x * vb5); vt = fmaf(a5.x, vt, -a5.y * vb5);
            float nb6 = fmaf(a6.y, vt, a6.x * vb6); vt = fmaf(a6.x, vt, -a6.y * vb6);
            float nb7 = fmaf(a7.y, vt, a7.x * vb7); vt = fmaf(a7.x, vt, -a7.y * vb7);

            Y[ib + 0][tid] = nb0; Y[ib + 1][tid] = nb1;
            Y[ib + 2][tid] = nb2; Y[ib + 3][tid] = nb3;
            Y[ib + 4][tid] = nb4; Y[ib + 5][tid] = nb5;
            Y[ib + 6][tid] = nb6; Y[ib + 7][tid] = nb7;
        }
        Y[t][tid] = vt;   // row t is final after fan t
    }
    __syncthreads();

    // g_R[k*64 + i] = mus[i] * R[i][k]; thread tid writes k = tid.
    for (int i = 0; i < NP; ++i) {
        g_R[tid * NP + i] = Y[i][tid] * mus[i];
    }
}

// ---------------------------------------------------------------------------
// Kernel 2: out[64, N] = R @ X via f32x2 packed FMA.  (unchanged from R6)
// Tile: 256 threads = 4 row-groups x 64 col-slots; thread = 16 rows x 2 cols.
// k runs in 8 batches of 8; batches ping-pong software-pipelined, all
// indices compile-time static.
// ---------------------------------------------------------------------------
__global__ __launch_bounds__(TPB, 3)
void apply_R_kernel(const float* __restrict__ X,
                    float* __restrict__ out,
                    int N) {
    __shared__ __align__(16) float Rs[NP * NP];
    for (int t = threadIdx.x; t < NP * NP; t += TPB) Rs[t] = g_R[t];
    __syncthreads();

    const int rg  = threadIdx.x >> 6;          // row group 0..3
    const int cl  = threadIdx.x & 63;          // column slot
    const int col = blockIdx.x * CPB + cl * 2;
    if (col >= N) return;                      // N % 2 == 0

    unsigned long long acc[8][2];
#pragma unroll
    for (int p = 0; p < 8; ++p) {
        acc[p][0] = 0ull;
        acc[p][1] = 0ull;
    }

    const ulonglong2* Rs2 = reinterpret_cast<const ulonglong2*>(Rs);
    const int rbase = rg * 4;
    const float* xp = X + col;

#define DO_K(kk, xv)                                                   \
    {                                                                  \
        unsigned long long xs0 = splat2((xv).x);                       \
        unsigned long long xs1 = splat2((xv).y);                       \
        ulonglong2 q0 = Rs2[(kk) * 16 + rbase + 0];                    \
        ulonglong2 q1 = Rs2[(kk) * 16 + rbase + 1];                    \
        ulonglong2 q2 = Rs2[(kk) * 16 + rbase + 2];                    \
        ulonglong2 q3 = Rs2[(kk) * 16 + rbase + 3];                    \
        acc[0][0] = ffma2(q0.x, xs0, acc[0][0]);                       \
        acc[0][1] = ffma2(q0.x, xs1, acc[0][1]);                       \
        acc[1][0] = ffma2(q0.y, xs0, acc[1][0]);                       \
        acc[1][1] = ffma2(q0.y, xs1, acc[1][1]);                       \
        acc[2][0] = ffma2(q1.x, xs0, acc[2][0]);                       \
        acc[2][1] = ffma2(q1.x, xs1, acc[2][1]);                       \
        acc[3][0] = ffma2(q1.y, xs0, acc[3][0]);                       \
        acc[3][1] = ffma2(q1.y, xs1, acc[3][1]);                       \
        acc[4][0] = ffma2(q2.x, xs0, acc[4][0]);                       \
        acc[4][1] = ffma2(q2.x, xs1, acc[4][1]);                       \
        acc[5][0] = ffma2(q2.y, xs0, acc[5][0]);                       \
        acc[5][1] = ffma2(q2.y, xs1, acc[5][1]);                       \
        acc[6][0] = ffma2(q3.x, xs0, acc[6][0]);                       \
        acc[6][1] = ffma2(q3.x, xs1, acc[6][1]);                       \
        acc[7][0] = ffma2(q3.y, xs0, acc[7][0]);                       \
        acc[7][1] = ffma2(q3.y, xs1, acc[7][1]);                       \
    }

#define LOADB(buf, b)                                                            \
    {                                                                            \
        _Pragma("unroll")                                                        \
        for (int u = 0; u < 8; ++u) {                                            \
            (buf)[u] = *reinterpret_cast<const float2*>(                         \
                xp + (size_t)((b) * 8 + u) * N);                                 \
        }                                                                        \
    }
#define COMPUTEB(buf, b)                                                         \
    {                                                                            \
        _Pragma("unroll")                                                        \
        for (int u = 0; u < 8; ++u) { DO_K((b) * 8 + u, (buf)[u]); }             \
    }

    float2 bufA[8], bufB[8];
    LOADB(bufA, 0);
#pragma unroll
    for (int bb = 0; bb < 4; ++bb) {
        const int b0 = 2 * bb, b1 = 2 * bb + 1;
        LOADB(bufB, b1);
        COMPUTEB(bufA, b0);
        if (b1 + 1 < 8) LOADB(bufA, b1 + 1);
        COMPUTEB(bufB, b1);
    }
#undef COMPUTEB
#undef LOADB
#undef DO_K

    const int row0 = rg * 16;
#pragma unroll
    for (int p = 0; p < 8; ++p) {
        float2 u0 = unpack2(acc[p][0]);
        float2 u1 = unpack2(acc[p][1]);
        float2 lo = make_float2(u0.x, u1.x);
        float2 hi = make_float2(u0.y, u1.y);
        *reinterpret_cast<float2*>(out + (size_t)(row0 + 2 * p + 0) * N + col) = lo;
        *reinterpret_cast<float2*>(out + (size_t)(row0 + 2 * p + 1) * N + col) = hi;
    }
}

// ---------------------------------------------------------------------------
// Inputs (metadata order): X [64*500000] f32, angles [2016] f32, mus [64] f32.
// Output: [64*500000] f32.
// ---------------------------------------------------------------------------
extern "C" void kernel_launch(void* const* d_in, const int* in_sizes, int n_in,
                              void* d_out, int out_size) {
    const float* X      = (const float*)d_in[0];
    const float* angles = (const float*)d_in[1];
    const float* mus    = (const float*)d_in[2];
    float* out = (float*)d_out;

    const int N = in_sizes[0] / NP;  // 500000

    build_R_kernel<<<1, NP>>>(angles, mus);

    int grid = (N + CPB - 1) / CPB;  // 128 columns per block
    apply_R_kernel<<<grid, TPB>>>(X, out, N);
}